// round 1
// baseline (speedup 1.0000x reference)
#include <cuda_runtime.h>
#include <cstdint>

// Problem constants (match reference)
#define NUM_CENTERS 1000
#define CAPACITY    512
#define FEAT_DIM    256
#define BATCH       65536

// FEAT_DIM floats = 64 float4 per row. 64 threads per row, 4 rows per 256-thread block.
#define VEC_PER_ROW   (FEAT_DIM / 4)   // 64
#define ROWS_PER_BLK  4
#define THREADS       (VEC_PER_ROW * ROWS_PER_BLK)  // 256

__global__ __launch_bounds__(THREADS)
void noise_bank_gather(const int* __restrict__ tgt,
                       const int* __restrict__ ridx,
                       const int* __restrict__ counts,
                       const float4* __restrict__ bank,
                       const float4* __restrict__ fallback,
                       float4* __restrict__ out)
{
    const int row_in_blk = threadIdx.x / VEC_PER_ROW;   // 0..3
    const int lane       = threadIdx.x % VEC_PER_ROW;   // 0..63
    const int sample     = blockIdx.x * ROWS_PER_BLK + row_in_blk;
    if (sample >= BATCH) return;

    const int c   = __ldg(&tgt[sample]);
    const int cnt = __ldg(&counts[c]);

    const float4* src;
    if (cnt > 0) {
        const int idx = __ldg(&ridx[sample]) % cnt;     // rand_idx in [0,512), cnt>0
        src = bank + ((int64_t)c * CAPACITY + idx) * VEC_PER_ROW;
    } else {
        src = fallback + (int64_t)sample * VEC_PER_ROW;
    }

    out[(int64_t)sample * VEC_PER_ROW + lane] = __ldg(&src[lane]);
}

extern "C" void kernel_launch(void* const* d_in, const int* in_sizes, int n_in,
                              void* d_out, int out_size)
{
    const int*    tgt      = (const int*)   d_in[0];  // target_center_ids [B]
    const int*    ridx     = (const int*)   d_in[1];  // rand_idx          [B]
    const int*    counts   = (const int*)   d_in[2];  // counts            [NUM_CENTERS]
    const float4* bank     = (const float4*)d_in[3];  // bank [NC, CAP, D]
    const float4* fallback = (const float4*)d_in[4];  // fallback_noise [B, D]
    float4*       out      = (float4*)      d_out;    // [B, D] fp32

    const int grid = (BATCH + ROWS_PER_BLK - 1) / ROWS_PER_BLK;  // 16384
    noise_bank_gather<<<grid, THREADS>>>(tgt, ridx, counts, bank, fallback, out);
}

// round 2
// speedup vs baseline: 1.5601x; 1.5601x over previous
#include <cuda_runtime.h>
#include <cstdint>

// Problem constants (match reference)
#define NUM_CENTERS 1000
#define CAPACITY    512
#define FEAT_DIM    256
#define BATCH       65536

#define VEC_PER_ROW     (FEAT_DIM / 4)       // 64 float4 per row (1 KB)
#define SAMPLES_PER_BLK 32
#define THREADS         256
#define TOTAL_VEC       (SAMPLES_PER_BLK * VEC_PER_ROW)   // 2048 float4
#define VEC_PER_THREAD  (TOTAL_VEC / THREADS)             // 8

__global__ __launch_bounds__(THREADS)
void noise_bank_gather(const int* __restrict__ tgt,
                       const int* __restrict__ ridx,
                       const int* __restrict__ counts,
                       const float4* __restrict__ bank,
                       const float4* __restrict__ fallback,
                       float4* __restrict__ out)
{
    __shared__ const float4* srcs[SAMPLES_PER_BLK];

    const int tid  = threadIdx.x;
    const int base = blockIdx.x * SAMPLES_PER_BLK;

    // Phase A: 32 threads resolve 32 independent source pointers.
    if (tid < SAMPLES_PER_BLK) {
        const int sample = base + tid;
        const int c   = __ldg(&tgt[sample]);
        const int cnt = __ldg(&counts[c]);
        const float4* p;
        if (cnt > 0) {
            const int idx = __ldg(&ridx[sample]) % cnt;
            p = bank + ((int64_t)c * CAPACITY + idx) * VEC_PER_ROW;
        } else {
            p = fallback + (int64_t)sample * VEC_PER_ROW;
        }
        srcs[tid] = p;
    }
    __syncthreads();

    // Phase B: copy 32 rows (32 KB). Each thread: 8 independent LDG.128.
    // v = k*256 + tid keeps each warp on a contiguous 512B slice of a row.
    float4* const out_base = out + (int64_t)base * VEC_PER_ROW;

    float4 v[VEC_PER_THREAD];
    #pragma unroll
    for (int k = 0; k < VEC_PER_THREAD; ++k) {
        const int pos  = k * THREADS + tid;         // 0..2047
        const int s    = pos >> 6;                  // sample within block
        const int lane = pos & (VEC_PER_ROW - 1);   // float4 within row
        v[k] = __ldg(&srcs[s][lane]);
    }
    #pragma unroll
    for (int k = 0; k < VEC_PER_THREAD; ++k) {
        const int pos = k * THREADS + tid;
        out_base[pos] = v[k];
    }
}

extern "C" void kernel_launch(void* const* d_in, const int* in_sizes, int n_in,
                              void* d_out, int out_size)
{
    const int*    tgt      = (const int*)   d_in[0];  // target_center_ids [B]
    const int*    ridx     = (const int*)   d_in[1];  // rand_idx          [B]
    const int*    counts   = (const int*)   d_in[2];  // counts            [NUM_CENTERS]
    const float4* bank     = (const float4*)d_in[3];  // bank [NC, CAP, D]
    const float4* fallback = (const float4*)d_in[4];  // fallback_noise [B, D]
    float4*       out      = (float4*)      d_out;    // [B, D] fp32

    const int grid = BATCH / SAMPLES_PER_BLK;  // 2048
    noise_bank_gather<<<grid, THREADS>>>(tgt, ridx, counts, bank, fallback, out);
}